// round 2
// baseline (speedup 1.0000x reference)
#include <cuda_runtime.h>
#include <math.h>

// ---------------------------------------------------------------------------
// Problem constants
// ---------------------------------------------------------------------------
#define R_RAYS   8192
#define S_SAMP   64
#define NSAMP    (R_RAYS * S_SAMP)   // 524288

// Per-combo: W (coeff width), W2 = 2W, PE = 128*W2*32, OFF (into g_planes)
// combos: (0,1) (0,2) (0,3) (1,2) (1,3) (2,3)
// widths: 64,64,50,64,50,50  ->  W2: 128,128,100,128,100,100
// PE:     524288,524288,409600,524288,409600,409600
// OFF (hi plane; lo plane at OFF+PE):
//   0, 1048576, 2097152, 2916352, 3964928, 4784128
#define TOTAL_PLANE_FLOATS 5603328   // 21.4 MB

// Scratch: precomputed IDWT planes, layout per plane: [Y][X][C=32]
__device__ float g_planes[TOTAL_PLANE_FLOATS];

// ---------------------------------------------------------------------------
// IDWT precompute: one thread per output (pixel, channel) of the hi plane,
// also writes the matching lo-plane value (lo = 0.5 * a, nearest-upsampled).
// ---------------------------------------------------------------------------
template <int W, int W2, int PE, int OFF>
__global__ void idwt_kernel(const float* __restrict__ yl,
                            const float* __restrict__ yh) {
    int idx = blockIdx.x * blockDim.x + threadIdx.x;
    if (idx >= PE) return;

    int c   = idx & 31;
    int pix = idx >> 5;
    int X   = pix % W2;
    int Y   = pix / W2;
    int i0  = Y >> 1, j0 = X >> 1;
    int dy  = Y & 1,  dx = X & 1;

    float a  = yl[(c * 64 + i0) * W + j0];
    float lh = yh[((c * 3 + 0) * 64 + i0) * W + j0];
    float hl = yh[((c * 3 + 1) * 64 + i0) * W + j0];
    float hh = yh[((c * 3 + 2) * 64 + i0) * W + j0];

    float s = a;
    s += dy ? -lh : lh;
    s += dx ? -hl : hl;
    s += (dy ^ dx) ? -hh : hh;

    g_planes[OFF + idx]      = 0.5f * s;   // hi plane
    g_planes[OFF + PE + idx] = 0.5f * a;   // lo plane
}

// ---------------------------------------------------------------------------
// Per-combo bilinear sample of hi & lo planes, multiplying into fh/fl.
// ---------------------------------------------------------------------------
template <int W2, int OFF, int PE, int J, int K>
__device__ __forceinline__ void sample_combo(const float p4[4],
                                             float fh[32], float fl[32]) {
    constexpr int LOQ = PE / 4;   // lo-plane offset in float4 units

    float y = (p4[J] + 1.0f) * 0.5f * 127.0f;
    float x = (p4[K] + 1.0f) * 0.5f * (float)(W2 - 1);

    float yf = fminf(fmaxf(floorf(y), 0.0f), 127.0f);
    float xf = fminf(fmaxf(floorf(x), 0.0f), (float)(W2 - 1));
    int y0 = (int)yf, x0 = (int)xf;
    int y1 = min(y0 + 1, 127);
    int x1 = min(x0 + 1, W2 - 1);
    float wy = fminf(fmaxf(y - yf, 0.0f), 1.0f);
    float wx = fminf(fmaxf(x - xf, 0.0f), 1.0f);

    float w00 = (1.0f - wy) * (1.0f - wx);
    float w01 = (1.0f - wy) * wx;
    float w10 = wy * (1.0f - wx);
    float w11 = wy * wx;

    const float4* q00 = (const float4*)(g_planes + OFF + (y0 * W2 + x0) * 32);
    const float4* q01 = (const float4*)(g_planes + OFF + (y0 * W2 + x1) * 32);
    const float4* q10 = (const float4*)(g_planes + OFF + (y1 * W2 + x0) * 32);
    const float4* q11 = (const float4*)(g_planes + OFF + (y1 * W2 + x1) * 32);

#pragma unroll
    for (int q = 0; q < 8; q++) {
        float4 a = q00[q], b = q01[q], c = q10[q], d = q11[q];
        fh[4*q+0] *= w00*a.x + w01*b.x + w10*c.x + w11*d.x;
        fh[4*q+1] *= w00*a.y + w01*b.y + w10*c.y + w11*d.y;
        fh[4*q+2] *= w00*a.z + w01*b.z + w10*c.z + w11*d.z;
        fh[4*q+3] *= w00*a.w + w01*b.w + w10*c.w + w11*d.w;

        float4 al = q00[q+LOQ], bl = q01[q+LOQ], cl = q10[q+LOQ], dl = q11[q+LOQ];
        fl[4*q+0] *= w00*al.x + w01*bl.x + w10*cl.x + w11*dl.x;
        fl[4*q+1] *= w00*al.y + w01*bl.y + w10*cl.y + w11*dl.y;
        fl[4*q+2] *= w00*al.z + w01*bl.z + w10*cl.z + w11*dl.z;
        fl[4*q+3] *= w00*al.w + w01*bl.w + w10*cl.w + w11*dl.w;
    }
}

// ---------------------------------------------------------------------------
// Main fused kernel: one thread per sample.
// ---------------------------------------------------------------------------
__global__ __launch_bounds__(128) void wf_main(
    const float* __restrict__ pts, const float* __restrict__ dirs,
    const float* __restrict__ ts,
    const float* __restrict__ Wsig1, const float* __restrict__ Wsig2,
    const float* __restrict__ Wc1, const float* __restrict__ Wc2,
    const float* __restrict__ Wc3, float* __restrict__ outp) {

    __shared__ float sW1[64 * 64];   // 16 KB
    __shared__ float sW2[64 * 16];   // 4 KB
    __shared__ float sC1[31 * 64];   // ~7.75 KB
    __shared__ float sC2[64 * 64];   // 16 KB
    __shared__ float sC3[64 * 3];    // 0.75 KB

    for (int i = threadIdx.x; i < 64*64; i += 128) sW1[i] = Wsig1[i];
    for (int i = threadIdx.x; i < 64*16; i += 128) sW2[i] = Wsig2[i];
    for (int i = threadIdx.x; i < 31*64; i += 128) sC1[i] = Wc1[i];
    for (int i = threadIdx.x; i < 64*64; i += 128) sC2[i] = Wc2[i];
    for (int i = threadIdx.x; i < 64*3;  i += 128) sC3[i] = Wc3[i];
    __syncthreads();

    int n = blockIdx.x * 128 + threadIdx.x;   // NSAMP divisible by 128
    int r = n >> 6;

    float p4[4];
    p4[0] = pts[3*n + 0];
    p4[1] = pts[3*n + 1];
    p4[2] = pts[3*n + 2];
    p4[3] = ts[r] * 2.0f - 1.0f;

    float fh[32], fl[32];
#pragma unroll
    for (int c = 0; c < 32; c++) { fh[c] = 1.0f; fl[c] = 1.0f; }

    // combos: (0,1) (0,2) (0,3) (1,2) (1,3) (2,3)
    sample_combo<128,       0, 524288, 0, 1>(p4, fh, fl);
    sample_combo<128, 1048576, 524288, 0, 2>(p4, fh, fl);
    sample_combo<100, 2097152, 409600, 0, 3>(p4, fh, fl);
    sample_combo<128, 2916352, 524288, 1, 2>(p4, fh, fl);
    sample_combo<100, 3964928, 409600, 1, 3>(p4, fh, fl);
    sample_combo<100, 4784128, 409600, 2, 3>(p4, fh, fl);

    // ---- MLP1: h = relu(concat(fh, fl) @ Wsig1[64,64]) ----
    float h[64];
#pragma unroll
    for (int o = 0; o < 64; o += 4) {
        float a0 = 0.f, a1 = 0.f, a2 = 0.f, a3 = 0.f;
#pragma unroll
        for (int i = 0; i < 32; i++) {
            float f = fh[i];
            float4 wv = *(const float4*)(sW1 + i * 64 + o);
            a0 += f * wv.x; a1 += f * wv.y; a2 += f * wv.z; a3 += f * wv.w;
        }
#pragma unroll
        for (int i = 0; i < 32; i++) {
            float f = fl[i];
            float4 wv = *(const float4*)(sW1 + (i + 32) * 64 + o);
            a0 += f * wv.x; a1 += f * wv.y; a2 += f * wv.z; a3 += f * wv.w;
        }
        h[o+0] = fmaxf(a0, 0.f);
        h[o+1] = fmaxf(a1, 0.f);
        h[o+2] = fmaxf(a2, 0.f);
        h[o+3] = fmaxf(a3, 0.f);
    }

    // ---- out = h @ Wsig2[64,16] (no relu) ----
    float ov[16];
#pragma unroll
    for (int o = 0; o < 16; o += 4) {
        float a0 = 0.f, a1 = 0.f, a2 = 0.f, a3 = 0.f;
#pragma unroll
        for (int i = 0; i < 64; i++) {
            float f = h[i];
            float4 wv = *(const float4*)(sW2 + i * 16 + o);
            a0 += f * wv.x; a1 += f * wv.y; a2 += f * wv.z; a3 += f * wv.w;
        }
        ov[o+0] = a0; ov[o+1] = a1; ov[o+2] = a2; ov[o+3] = a3;
    }
    float density = expf(fminf(fmaxf(ov[15], -15.0f), 15.0f));

    // ---- SH degree-4 encoding of normalized direction ----
    float dxv = dirs[3*r + 0], dyv = dirs[3*r + 1], dzv = dirs[3*r + 2];
    float inv = rsqrtf(dxv*dxv + dyv*dyv + dzv*dzv);
    float X = dxv * inv, Y = dyv * inv, Z = dzv * inv;
    float xx = X * X, yy = Y * Y, zz = Z * Z;

    float ci[31];
    ci[0]  = 0.28209479177387814f;
    ci[1]  = -0.4886025119029199f * Y;
    ci[2]  = 0.4886025119029199f * Z;
    ci[3]  = -0.4886025119029199f * X;
    ci[4]  = 1.0925484305920792f * X * Y;
    ci[5]  = -1.0925484305920792f * Y * Z;
    ci[6]  = 0.31539156525252005f * (3.0f * zz - 1.0f);
    ci[7]  = -1.0925484305920792f * X * Z;
    ci[8]  = 0.5462742152960396f * (xx - yy);
    ci[9]  = -0.5900435899266435f * Y * (3.0f * xx - yy);
    ci[10] = 2.890611442640554f * X * Y * Z;
    ci[11] = -0.4570457994644658f * Y * (5.0f * zz - 1.0f);
    ci[12] = 0.3731763325901154f * Z * (5.0f * zz - 3.0f);
    ci[13] = -0.4570457994644658f * X * (5.0f * zz - 1.0f);
    ci[14] = 1.445305721320277f * Z * (xx - yy);
    ci[15] = -0.5900435899266435f * X * (xx - 3.0f * yy);
#pragma unroll
    for (int g = 0; g < 15; g++) ci[16 + g] = ov[g];

    // ---- h2 = relu(ci @ Wc1[31,64]) ----
    float h2[64];
#pragma unroll
    for (int o = 0; o < 64; o += 4) {
        float a0 = 0.f, a1 = 0.f, a2 = 0.f, a3 = 0.f;
#pragma unroll
        for (int i = 0; i < 31; i++) {
            float f = ci[i];
            float4 wv = *(const float4*)(sC1 + i * 64 + o);
            a0 += f * wv.x; a1 += f * wv.y; a2 += f * wv.z; a3 += f * wv.w;
        }
        h2[o+0] = fmaxf(a0, 0.f);
        h2[o+1] = fmaxf(a1, 0.f);
        h2[o+2] = fmaxf(a2, 0.f);
        h2[o+3] = fmaxf(a3, 0.f);
    }

    // ---- h3 = relu(h2 @ Wc2[64,64]) ----
    float h3[64];
#pragma unroll
    for (int o = 0; o < 64; o += 4) {
        float a0 = 0.f, a1 = 0.f, a2 = 0.f, a3 = 0.f;
#pragma unroll
        for (int i = 0; i < 64; i++) {
            float f = h2[i];
            float4 wv = *(const float4*)(sC2 + i * 64 + o);
            a0 += f * wv.x; a1 += f * wv.y; a2 += f * wv.z; a3 += f * wv.w;
        }
        h3[o+0] = fmaxf(a0, 0.f);
        h3[o+1] = fmaxf(a1, 0.f);
        h3[o+2] = fmaxf(a2, 0.f);
        h3[o+3] = fmaxf(a3, 0.f);
    }

    // ---- rgb = sigmoid(h3 @ Wc3[64,3]) ----
    float r0 = 0.f, r1 = 0.f, r2 = 0.f;
#pragma unroll
    for (int i = 0; i < 64; i++) {
        float f = h3[i];
        r0 += f * sC3[i * 3 + 0];
        r1 += f * sC3[i * 3 + 1];
        r2 += f * sC3[i * 3 + 2];
    }

    float4 res;
    res.x = 1.0f / (1.0f + expf(-r0));
    res.y = 1.0f / (1.0f + expf(-r1));
    res.z = 1.0f / (1.0f + expf(-r2));
    res.w = density;
    *(float4*)(outp + 4 * n) = res;
}

// ---------------------------------------------------------------------------
// Launch
// ---------------------------------------------------------------------------
extern "C" void kernel_launch(void* const* d_in, const int* in_sizes, int n_in,
                              void* d_out, int out_size) {
    const float* pts  = (const float*)d_in[0];
    const float* dirs = (const float*)d_in[1];
    const float* ts   = (const float*)d_in[2];
    const float* yl0 = (const float*)d_in[3];  const float* yh0 = (const float*)d_in[4];
    const float* yl1 = (const float*)d_in[5];  const float* yh1 = (const float*)d_in[6];
    const float* yl2 = (const float*)d_in[7];  const float* yh2 = (const float*)d_in[8];
    const float* yl3 = (const float*)d_in[9];  const float* yh3 = (const float*)d_in[10];
    const float* yl4 = (const float*)d_in[11]; const float* yh4 = (const float*)d_in[12];
    const float* yl5 = (const float*)d_in[13]; const float* yh5 = (const float*)d_in[14];
    const float* Wsig1 = (const float*)d_in[15];
    const float* Wsig2 = (const float*)d_in[16];
    const float* Wc1   = (const float*)d_in[17];
    const float* Wc2   = (const float*)d_in[18];
    const float* Wc3   = (const float*)d_in[19];

    idwt_kernel<64, 128, 524288,       0><<<524288 / 256, 256>>>(yl0, yh0);
    idwt_kernel<64, 128, 524288, 1048576><<<524288 / 256, 256>>>(yl1, yh1);
    idwt_kernel<50, 100, 409600, 2097152><<<409600 / 256, 256>>>(yl2, yh2);
    idwt_kernel<64, 128, 524288, 2916352><<<524288 / 256, 256>>>(yl3, yh3);
    idwt_kernel<50, 100, 409600, 3964928><<<409600 / 256, 256>>>(yl4, yh4);
    idwt_kernel<50, 100, 409600, 4784128><<<409600 / 256, 256>>>(yl5, yh5);

    wf_main<<<NSAMP / 128, 128>>>(pts, dirs, ts, Wsig1, Wsig2, Wc1, Wc2, Wc3,
                                  (float*)d_out);
}

// round 4
// speedup vs baseline: 1.5024x; 1.5024x over previous
#include <cuda_runtime.h>
#include <math.h>

// ---------------------------------------------------------------------------
// Problem constants
// ---------------------------------------------------------------------------
#define NSAMP    524288      // 8192 rays * 64 samples

// combos: (0,1) (0,2) (0,3) (1,2) (1,3) (2,3)
// widths: 64,64,50,64,50,50  ->  W2: 128,128,100,128,100,100
// PE = 128*W2*32:  524288,524288,409600,524288,409600,409600
#define TOTAL_PLANE_FLOATS 5603328   // 21.4 MB

// Precomputed IDWT planes, per-plane layout [Y][X][C=32] (channel-contiguous)
__device__ float g_planes[TOTAL_PLANE_FLOATS];
// Feature scratch, feature-major: g_feats[f * NSAMP + n], f in [0,64)
__device__ float g_feats[64 * NSAMP];          // 134 MB

// ---------------------------------------------------------------------------
// IDWT precompute: one thread per (channel, coeff-pixel) -> writes 2x2 output
// quad for hi plane and lo plane. All 4 coefficient reads coalesced.
// ---------------------------------------------------------------------------
template <int W, int W2, int PE, int OFF>
__global__ void idwt_kernel(const float* __restrict__ yl,
                            const float* __restrict__ yh) {
    int idx = blockIdx.x * blockDim.x + threadIdx.x;
    if (idx >= 32 * 64 * W) return;

    int j0   = idx % W;
    int rest = idx / W;
    int i0   = rest & 63;
    int c    = rest >> 6;

    float a  = yl[(c * 64 + i0) * W + j0];
    float lh = yh[((c * 3 + 0) * 64 + i0) * W + j0];
    float hl = yh[((c * 3 + 1) * 64 + i0) * W + j0];
    float hh = yh[((c * 3 + 2) * 64 + i0) * W + j0];

    float ee = 0.5f * (a + lh + hl + hh);
    float eo = 0.5f * (a + lh - hl - hh);
    float oe = 0.5f * (a - lh + hl - hh);
    float oo = 0.5f * (a - lh - hl + hh);
    float lo = 0.5f * a;

    int base = OFF + ((2 * i0) * W2 + 2 * j0) * 32 + c;
    float* gp = g_planes;
    gp[base]                = ee;
    gp[base + 32]           = eo;
    gp[base + W2 * 32]      = oe;
    gp[base + W2 * 32 + 32] = oo;

    int lbase = base + PE;
    gp[lbase]                = lo;
    gp[lbase + 32]           = lo;
    gp[lbase + W2 * 32]      = lo;
    gp[lbase + W2 * 32 + 32] = lo;
}

// ---------------------------------------------------------------------------
// Warp-cooperative bilinear sample: all 32 lanes load the 32-channel vector
// of each corner as one coalesced 128B line. lane == channel.
// ---------------------------------------------------------------------------
template <int W2, int OFF, int PE, int J, int K>
__device__ __forceinline__ void sample2(const float q[4], int lane,
                                        float& prodH, float& prodL) {
    const float* __restrict__ gp = g_planes;

    float y = (q[J] + 1.0f) * 0.5f * 127.0f;
    float x = (q[K] + 1.0f) * 0.5f * (float)(W2 - 1);

    float yf = fminf(fmaxf(floorf(y), 0.0f), 127.0f);
    float xf = fminf(fmaxf(floorf(x), 0.0f), (float)(W2 - 1));
    int y0 = (int)yf, x0 = (int)xf;
    int y1 = min(y0 + 1, 127);
    int x1 = min(x0 + 1, W2 - 1);
    float wy = fminf(fmaxf(y - yf, 0.0f), 1.0f);
    float wx = fminf(fmaxf(x - xf, 0.0f), 1.0f);

    float w00 = (1.0f - wy) * (1.0f - wx);
    float w01 = (1.0f - wy) * wx;
    float w10 = wy * (1.0f - wx);
    float w11 = wy * wx;

    int b00 = OFF + (y0 * W2 + x0) * 32 + lane;
    int b01 = OFF + (y0 * W2 + x1) * 32 + lane;
    int b10 = OFF + (y1 * W2 + x0) * 32 + lane;
    int b11 = OFF + (y1 * W2 + x1) * 32 + lane;

    float h00 = gp[b00], h01 = gp[b01], h10 = gp[b10], h11 = gp[b11];
    float l00 = gp[b00 + PE], l01 = gp[b01 + PE], l10 = gp[b10 + PE], l11 = gp[b11 + PE];

    prodH *= w00 * h00 + w01 * h01 + w10 * h10 + w11 * h11;
    prodL *= w00 * l00 + w01 * l01 + w10 * l10 + w11 * l11;
}

// ---------------------------------------------------------------------------
// Kernel A: warp-cooperative gather -> feature-major global scratch.
// Block = 128 threads = 4 warps = 128 samples. Dynamic smem only (33.3 KB).
// ---------------------------------------------------------------------------
#define FSTRIDE 65   // transpose-stage row stride (bank-conflict-free)

__global__ __launch_bounds__(128) void wf_gather(
    const float* __restrict__ pts, const float* __restrict__ ts) {

    extern __shared__ float feats[];   // 128 * FSTRIDE floats

    int lane = threadIdx.x & 31;
    int warp = threadIdx.x >> 5;
    int n = blockIdx.x * 128 + threadIdx.x;

    float px = pts[3*n + 0];
    float py = pts[3*n + 1];
    float pz = pts[3*n + 2];
    float pt = ts[n >> 6] * 2.0f - 1.0f;

    float* wf = feats + warp * 32 * FSTRIDE;

#pragma unroll 1
    for (int s = 0; s < 32; s++) {
        float q[4];
        q[0] = __shfl_sync(0xffffffffu, px, s);
        q[1] = __shfl_sync(0xffffffffu, py, s);
        q[2] = __shfl_sync(0xffffffffu, pz, s);
        q[3] = __shfl_sync(0xffffffffu, pt, s);

        float prodH = 1.0f, prodL = 1.0f;
        sample2<128,       0, 524288, 0, 1>(q, lane, prodH, prodL);
        sample2<128, 1048576, 524288, 0, 2>(q, lane, prodH, prodL);
        sample2<100, 2097152, 409600, 0, 3>(q, lane, prodH, prodL);
        sample2<128, 2916352, 524288, 1, 2>(q, lane, prodH, prodL);
        sample2<100, 3964928, 409600, 1, 3>(q, lane, prodH, prodL);
        sample2<100, 4784128, 409600, 2, 3>(q, lane, prodH, prodL);

        wf[s * FSTRIDE + lane]      = prodH;
        wf[s * FSTRIDE + 32 + lane] = prodL;
    }
    __syncwarp();

    // Coalesced feature-major stores: fixed f -> consecutive n.
#pragma unroll
    for (int f = 0; f < 64; f++) {
        g_feats[f * NSAMP + n] = wf[lane * FSTRIDE + f];
    }
}

// ---------------------------------------------------------------------------
// Kernel B: register-resident MLP chain. Static smem weights (44.5 KB).
// ---------------------------------------------------------------------------
__global__ __launch_bounds__(128) void wf_mlp(
    const float* __restrict__ dirs,
    const float* __restrict__ Wsig1, const float* __restrict__ Wsig2,
    const float* __restrict__ Wc1, const float* __restrict__ Wc2,
    const float* __restrict__ Wc3, float* __restrict__ outp) {

    __shared__ float sW1[64 * 64];   // 16 KB
    __shared__ float sW2[64 * 16];   // 4 KB
    __shared__ float sC1[31 * 64];   // 7.75 KB
    __shared__ float sC2[64 * 64];   // 16 KB
    __shared__ float sC3[64 * 3];    // 0.75 KB

    for (int i = threadIdx.x; i < 64*64; i += 128) sW1[i] = Wsig1[i];
    for (int i = threadIdx.x; i < 64*16; i += 128) sW2[i] = Wsig2[i];
    for (int i = threadIdx.x; i < 31*64; i += 128) sC1[i] = Wc1[i];
    for (int i = threadIdx.x; i < 64*64; i += 128) sC2[i] = Wc2[i];
    for (int i = threadIdx.x; i < 64*3;  i += 128) sC3[i] = Wc3[i];
    __syncthreads();

    int n = blockIdx.x * 128 + threadIdx.x;

    // Coalesced feature-major loads.
    float fv[64];
#pragma unroll
    for (int i = 0; i < 64; i++) fv[i] = g_feats[i * NSAMP + n];

    // ---- MLP1: h = relu(fv @ Wsig1[64,64]) ----
    float h[64];
#pragma unroll
    for (int o = 0; o < 64; o += 4) {
        float a0 = 0.f, a1 = 0.f, a2 = 0.f, a3 = 0.f;
#pragma unroll
        for (int i = 0; i < 64; i++) {
            float f = fv[i];
            float4 wv = *(const float4*)(sW1 + i * 64 + o);
            a0 += f * wv.x; a1 += f * wv.y; a2 += f * wv.z; a3 += f * wv.w;
        }
        h[o+0] = fmaxf(a0, 0.f);
        h[o+1] = fmaxf(a1, 0.f);
        h[o+2] = fmaxf(a2, 0.f);
        h[o+3] = fmaxf(a3, 0.f);
    }

    // ---- out = h @ Wsig2[64,16] ----
    float ov[16];
#pragma unroll
    for (int o = 0; o < 16; o += 4) {
        float a0 = 0.f, a1 = 0.f, a2 = 0.f, a3 = 0.f;
#pragma unroll
        for (int i = 0; i < 64; i++) {
            float f = h[i];
            float4 wv = *(const float4*)(sW2 + i * 16 + o);
            a0 += f * wv.x; a1 += f * wv.y; a2 += f * wv.z; a3 += f * wv.w;
        }
        ov[o+0] = a0; ov[o+1] = a1; ov[o+2] = a2; ov[o+3] = a3;
    }
    float density = expf(fminf(fmaxf(ov[15], -15.0f), 15.0f));

    // ---- SH degree-4 encoding of normalized direction ----
    int r = n >> 6;
    float dxv = dirs[3*r + 0], dyv = dirs[3*r + 1], dzv = dirs[3*r + 2];
    float inv = rsqrtf(dxv*dxv + dyv*dyv + dzv*dzv);
    float X = dxv * inv, Y = dyv * inv, Z = dzv * inv;
    float xx = X * X, yy = Y * Y, zz = Z * Z;

    float ci[31];
    ci[0]  = 0.28209479177387814f;
    ci[1]  = -0.4886025119029199f * Y;
    ci[2]  = 0.4886025119029199f * Z;
    ci[3]  = -0.4886025119029199f * X;
    ci[4]  = 1.0925484305920792f * X * Y;
    ci[5]  = -1.0925484305920792f * Y * Z;
    ci[6]  = 0.31539156525252005f * (3.0f * zz - 1.0f);
    ci[7]  = -1.0925484305920792f * X * Z;
    ci[8]  = 0.5462742152960396f * (xx - yy);
    ci[9]  = -0.5900435899266435f * Y * (3.0f * xx - yy);
    ci[10] = 2.890611442640554f * X * Y * Z;
    ci[11] = -0.4570457994644658f * Y * (5.0f * zz - 1.0f);
    ci[12] = 0.3731763325901154f * Z * (5.0f * zz - 3.0f);
    ci[13] = -0.4570457994644658f * X * (5.0f * zz - 1.0f);
    ci[14] = 1.445305721320277f * Z * (xx - yy);
    ci[15] = -0.5900435899266435f * X * (xx - 3.0f * yy);
#pragma unroll
    for (int g = 0; g < 15; g++) ci[16 + g] = ov[g];

    // ---- h2 = relu(ci @ Wc1[31,64]) ----
    float h2[64];
#pragma unroll
    for (int o = 0; o < 64; o += 4) {
        float a0 = 0.f, a1 = 0.f, a2 = 0.f, a3 = 0.f;
#pragma unroll
        for (int i = 0; i < 31; i++) {
            float f = ci[i];
            float4 wv = *(const float4*)(sC1 + i * 64 + o);
            a0 += f * wv.x; a1 += f * wv.y; a2 += f * wv.z; a3 += f * wv.w;
        }
        h2[o+0] = fmaxf(a0, 0.f);
        h2[o+1] = fmaxf(a1, 0.f);
        h2[o+2] = fmaxf(a2, 0.f);
        h2[o+3] = fmaxf(a3, 0.f);
    }

    // ---- h3 = relu(h2 @ Wc2[64,64]) ----
    float h3[64];
#pragma unroll
    for (int o = 0; o < 64; o += 4) {
        float a0 = 0.f, a1 = 0.f, a2 = 0.f, a3 = 0.f;
#pragma unroll
        for (int i = 0; i < 64; i++) {
            float f = h2[i];
            float4 wv = *(const float4*)(sC2 + i * 64 + o);
            a0 += f * wv.x; a1 += f * wv.y; a2 += f * wv.z; a3 += f * wv.w;
        }
        h3[o+0] = fmaxf(a0, 0.f);
        h3[o+1] = fmaxf(a1, 0.f);
        h3[o+2] = fmaxf(a2, 0.f);
        h3[o+3] = fmaxf(a3, 0.f);
    }

    // ---- rgb = sigmoid(h3 @ Wc3[64,3]) ----
    float r0 = 0.f, r1 = 0.f, r2 = 0.f;
#pragma unroll
    for (int i = 0; i < 64; i++) {
        float f = h3[i];
        r0 += f * sC3[i * 3 + 0];
        r1 += f * sC3[i * 3 + 1];
        r2 += f * sC3[i * 3 + 2];
    }

    float4 res;
    res.x = 1.0f / (1.0f + expf(-r0));
    res.y = 1.0f / (1.0f + expf(-r1));
    res.z = 1.0f / (1.0f + expf(-r2));
    res.w = density;
    *(float4*)(outp + 4 * n) = res;
}

// ---------------------------------------------------------------------------
// Launch
// ---------------------------------------------------------------------------
extern "C" void kernel_launch(void* const* d_in, const int* in_sizes, int n_in,
                              void* d_out, int out_size) {
    const float* pts  = (const float*)d_in[0];
    const float* dirs = (const float*)d_in[1];
    const float* ts   = (const float*)d_in[2];
    const float* yl0 = (const float*)d_in[3];  const float* yh0 = (const float*)d_in[4];
    const float* yl1 = (const float*)d_in[5];  const float* yh1 = (const float*)d_in[6];
    const float* yl2 = (const float*)d_in[7];  const float* yh2 = (const float*)d_in[8];
    const float* yl3 = (const float*)d_in[9];  const float* yh3 = (const float*)d_in[10];
    const float* yl4 = (const float*)d_in[11]; const float* yh4 = (const float*)d_in[12];
    const float* yl5 = (const float*)d_in[13]; const float* yh5 = (const float*)d_in[14];
    const float* Wsig1 = (const float*)d_in[15];
    const float* Wsig2 = (const float*)d_in[16];
    const float* Wc1   = (const float*)d_in[17];
    const float* Wc2   = (const float*)d_in[18];
    const float* Wc3   = (const float*)d_in[19];

    // threads per idwt = 32*64*W
    idwt_kernel<64, 128, 524288,       0><<<(32*64*64 + 255)/256, 256>>>(yl0, yh0);
    idwt_kernel<64, 128, 524288, 1048576><<<(32*64*64 + 255)/256, 256>>>(yl1, yh1);
    idwt_kernel<50, 100, 409600, 2097152><<<(32*64*50 + 255)/256, 256>>>(yl2, yh2);
    idwt_kernel<64, 128, 524288, 2916352><<<(32*64*64 + 255)/256, 256>>>(yl3, yh3);
    idwt_kernel<50, 100, 409600, 3964928><<<(32*64*50 + 255)/256, 256>>>(yl4, yh4);
    idwt_kernel<50, 100, 409600, 4784128><<<(32*64*50 + 255)/256, 256>>>(yl5, yh5);

    size_t dyn = 128 * FSTRIDE * sizeof(float);   // 33.3 KB dynamic only
    wf_gather<<<NSAMP / 128, 128, dyn>>>(pts, ts);

    wf_mlp<<<NSAMP / 128, 128>>>(dirs, Wsig1, Wsig2, Wc1, Wc2, Wc3,
                                 (float*)d_out);
}

// round 5
// speedup vs baseline: 1.8404x; 1.2250x over previous
#include <cuda_runtime.h>
#include <math.h>

// ---------------------------------------------------------------------------
// Problem constants
// ---------------------------------------------------------------------------
#define NSAMP    524288      // 8192 rays * 64 samples

// combos: (0,1) (0,2) (0,3) (1,2) (1,3) (2,3)
// widths: 64,64,50,64,50,50  ->  W2: 128,128,100,128,100,100
// PE = 128*W2*32:  524288,524288,409600,524288,409600,409600
#define TOTAL_PLANE_FLOATS 5603328   // 21.4 MB

__device__ float g_planes[TOTAL_PLANE_FLOATS];
__device__ float g_feats[64 * NSAMP];          // 134 MB, feature-major

// ---------------------------------------------------------------------------
// Packed dual-fp32 helpers (sm_100 f32x2 pipe; IEEE-identical to FFMA)
// ---------------------------------------------------------------------------
__device__ __forceinline__ unsigned long long pack2(float f) {
    unsigned long long r;
    asm("mov.b64 %0, {%1, %1};" : "=l"(r) : "f"(f));
    return r;
}
__device__ __forceinline__ void ffma2(unsigned long long& d,
                                      unsigned long long a,
                                      unsigned long long b) {
    asm("fma.rn.f32x2 %0, %1, %2, %0;" : "+l"(d) : "l"(a), "l"(b));
}
__device__ __forceinline__ void unpack2(unsigned long long v, float& lo, float& hi) {
    asm("mov.b64 {%0, %1}, %2;" : "=f"(lo), "=f"(hi) : "l"(v));
}

// ---------------------------------------------------------------------------
// IDWT precompute, all 6 combos in ONE kernel (block-range dispatch).
// One thread per (channel, coeff-pixel) -> writes 2x2 quad of hi & lo planes.
// ---------------------------------------------------------------------------
template <int W, int W2, int PE, int OFF>
__device__ __forceinline__ void idwt_body(const float* __restrict__ yl,
                                          const float* __restrict__ yh,
                                          int idx) {
    if (idx >= 32 * 64 * W) return;

    int j0   = idx % W;
    int rest = idx / W;
    int i0   = rest & 63;
    int c    = rest >> 6;

    float a  = yl[(c * 64 + i0) * W + j0];
    float lh = yh[((c * 3 + 0) * 64 + i0) * W + j0];
    float hl = yh[((c * 3 + 1) * 64 + i0) * W + j0];
    float hh = yh[((c * 3 + 2) * 64 + i0) * W + j0];

    float ee = 0.5f * (a + lh + hl + hh);
    float eo = 0.5f * (a + lh - hl - hh);
    float oe = 0.5f * (a - lh + hl - hh);
    float oo = 0.5f * (a - lh - hl + hh);
    float lo = 0.5f * a;

    int base = OFF + ((2 * i0) * W2 + 2 * j0) * 32 + c;
    float* gp = g_planes;
    gp[base]                = ee;
    gp[base + 32]           = eo;
    gp[base + W2 * 32]      = oe;
    gp[base + W2 * 32 + 32] = oo;

    int lbase = base + PE;
    gp[lbase]                = lo;
    gp[lbase + 32]           = lo;
    gp[lbase + W2 * 32]      = lo;
    gp[lbase + W2 * 32 + 32] = lo;
}

// block ranges (256 thr/blk): c0 [0,512) c1 [512,1024) c2 [1024,1424)
//                             c3 [1424,1936) c4 [1936,2336) c5 [2336,2736)
__global__ __launch_bounds__(256) void idwt_all(
    const float* __restrict__ yl0, const float* __restrict__ yh0,
    const float* __restrict__ yl1, const float* __restrict__ yh1,
    const float* __restrict__ yl2, const float* __restrict__ yh2,
    const float* __restrict__ yl3, const float* __restrict__ yh3,
    const float* __restrict__ yl4, const float* __restrict__ yh4,
    const float* __restrict__ yl5, const float* __restrict__ yh5) {
    int b = blockIdx.x;
    int t = threadIdx.x;
    if      (b <  512) idwt_body<64, 128, 524288,       0>(yl0, yh0, (b       ) * 256 + t);
    else if (b < 1024) idwt_body<64, 128, 524288, 1048576>(yl1, yh1, (b -  512) * 256 + t);
    else if (b < 1424) idwt_body<50, 100, 409600, 2097152>(yl2, yh2, (b - 1024) * 256 + t);
    else if (b < 1936) idwt_body<64, 128, 524288, 2916352>(yl3, yh3, (b - 1424) * 256 + t);
    else if (b < 2336) idwt_body<50, 100, 409600, 3964928>(yl4, yh4, (b - 1936) * 256 + t);
    else               idwt_body<50, 100, 409600, 4784128>(yl5, yh5, (b - 2336) * 256 + t);
}

// ---------------------------------------------------------------------------
// Warp-cooperative bilinear sample (lane == channel, coalesced 128B lines)
// ---------------------------------------------------------------------------
template <int W2, int OFF, int PE, int J, int K>
__device__ __forceinline__ void sample2(const float q[4], int lane,
                                        float& prodH, float& prodL) {
    const float* __restrict__ gp = g_planes;

    float y = (q[J] + 1.0f) * 0.5f * 127.0f;
    float x = (q[K] + 1.0f) * 0.5f * (float)(W2 - 1);

    float yf = fminf(fmaxf(floorf(y), 0.0f), 127.0f);
    float xf = fminf(fmaxf(floorf(x), 0.0f), (float)(W2 - 1));
    int y0 = (int)yf, x0 = (int)xf;
    int y1 = min(y0 + 1, 127);
    int x1 = min(x0 + 1, W2 - 1);
    float wy = fminf(fmaxf(y - yf, 0.0f), 1.0f);
    float wx = fminf(fmaxf(x - xf, 0.0f), 1.0f);

    float w00 = (1.0f - wy) * (1.0f - wx);
    float w01 = (1.0f - wy) * wx;
    float w10 = wy * (1.0f - wx);
    float w11 = wy * wx;

    int b00 = OFF + (y0 * W2 + x0) * 32 + lane;
    int b01 = OFF + (y0 * W2 + x1) * 32 + lane;
    int b10 = OFF + (y1 * W2 + x0) * 32 + lane;
    int b11 = OFF + (y1 * W2 + x1) * 32 + lane;

    float h00 = gp[b00], h01 = gp[b01], h10 = gp[b10], h11 = gp[b11];
    float l00 = gp[b00 + PE], l01 = gp[b01 + PE], l10 = gp[b10 + PE], l11 = gp[b11 + PE];

    prodH *= w00 * h00 + w01 * h01 + w10 * h10 + w11 * h11;
    prodL *= w00 * l00 + w01 * l01 + w10 * l10 + w11 * l11;
}

// ---------------------------------------------------------------------------
// Kernel A: gather -> feature-major scratch. 128 thr/blk, 33.3 KB dyn smem.
// ---------------------------------------------------------------------------
#define FSTRIDE 65

__global__ __launch_bounds__(128) void wf_gather(
    const float* __restrict__ pts, const float* __restrict__ ts) {

    extern __shared__ float feats[];

    int lane = threadIdx.x & 31;
    int warp = threadIdx.x >> 5;
    int n = blockIdx.x * 128 + threadIdx.x;

    float px = pts[3*n + 0];
    float py = pts[3*n + 1];
    float pz = pts[3*n + 2];
    float pt = ts[n >> 6] * 2.0f - 1.0f;

    float* wf = feats + warp * 32 * FSTRIDE;

#pragma unroll 1
    for (int s = 0; s < 32; s++) {
        float q[4];
        q[0] = __shfl_sync(0xffffffffu, px, s);
        q[1] = __shfl_sync(0xffffffffu, py, s);
        q[2] = __shfl_sync(0xffffffffu, pz, s);
        q[3] = __shfl_sync(0xffffffffu, pt, s);

        float prodH = 1.0f, prodL = 1.0f;
        sample2<128,       0, 524288, 0, 1>(q, lane, prodH, prodL);
        sample2<128, 1048576, 524288, 0, 2>(q, lane, prodH, prodL);
        sample2<100, 2097152, 409600, 0, 3>(q, lane, prodH, prodL);
        sample2<128, 2916352, 524288, 1, 2>(q, lane, prodH, prodL);
        sample2<100, 3964928, 409600, 1, 3>(q, lane, prodH, prodL);
        sample2<100, 4784128, 409600, 2, 3>(q, lane, prodH, prodL);

        wf[s * FSTRIDE + lane]      = prodH;
        wf[s * FSTRIDE + 32 + lane] = prodL;
    }
    __syncwarp();

#pragma unroll
    for (int f = 0; f < 64; f++) {
        g_feats[f * NSAMP + n] = wf[lane * FSTRIDE + f];
    }
}

// ---------------------------------------------------------------------------
// Kernel B: MLP chain with packed f32x2 FFMA. Static smem weights (44.5 KB).
// ---------------------------------------------------------------------------
__global__ __launch_bounds__(128) void wf_mlp(
    const float* __restrict__ dirs,
    const float* __restrict__ Wsig1, const float* __restrict__ Wsig2,
    const float* __restrict__ Wc1, const float* __restrict__ Wc2,
    const float* __restrict__ Wc3, float* __restrict__ outp) {

    __shared__ __align__(16) float sW1[64 * 64];
    __shared__ __align__(16) float sW2[64 * 16];
    __shared__ __align__(16) float sC1[32 * 64];   // padded row for alignment
    __shared__ __align__(16) float sC2[64 * 64];
    __shared__ float sC3[64 * 3];

    for (int i = threadIdx.x; i < 64*64; i += 128) sW1[i] = Wsig1[i];
    for (int i = threadIdx.x; i < 64*16; i += 128) sW2[i] = Wsig2[i];
    for (int i = threadIdx.x; i < 31*64; i += 128) sC1[i] = Wc1[i];
    for (int i = threadIdx.x; i < 64*64; i += 128) sC2[i] = Wc2[i];
    for (int i = threadIdx.x; i < 64*3;  i += 128) sC3[i] = Wc3[i];
    __syncthreads();

    int n = blockIdx.x * 128 + threadIdx.x;

    // Coalesced feature-major loads.
    float fv[64];
#pragma unroll
    for (int i = 0; i < 64; i++) fv[i] = g_feats[i * NSAMP + n];

    // ---- MLP1: h = relu(fv @ Wsig1[64,64]) --- packed f32x2 ----
    float h[64];
    {
        unsigned long long acc[32];
#pragma unroll
        for (int k = 0; k < 32; k++) acc[k] = 0ull;
#pragma unroll
        for (int i = 0; i < 64; i++) {
            unsigned long long fp = pack2(fv[i]);
            const ulonglong2* wrow = (const ulonglong2*)(sW1 + i * 64);
#pragma unroll
            for (int og = 0; og < 16; og++) {
                ulonglong2 w = wrow[og];
                ffma2(acc[2*og],     fp, w.x);
                ffma2(acc[2*og + 1], fp, w.y);
            }
        }
#pragma unroll
        for (int k = 0; k < 32; k++) {
            float lo, hi;
            unpack2(acc[k], lo, hi);
            h[2*k]   = fmaxf(lo, 0.f);
            h[2*k+1] = fmaxf(hi, 0.f);
        }
    }

    // ---- out = h @ Wsig2[64,16] --- packed f32x2 ----
    float ov[16];
    {
        unsigned long long acc[8];
#pragma unroll
        for (int k = 0; k < 8; k++) acc[k] = 0ull;
#pragma unroll
        for (int i = 0; i < 64; i++) {
            unsigned long long fp = pack2(h[i]);
            const ulonglong2* wrow = (const ulonglong2*)(sW2 + i * 16);
#pragma unroll
            for (int og = 0; og < 4; og++) {
                ulonglong2 w = wrow[og];
                ffma2(acc[2*og],     fp, w.x);
                ffma2(acc[2*og + 1], fp, w.y);
            }
        }
#pragma unroll
        for (int k = 0; k < 8; k++) unpack2(acc[k], ov[2*k], ov[2*k+1]);
    }
    float density = expf(fminf(fmaxf(ov[15], -15.0f), 15.0f));

    // ---- SH degree-4 encoding ----
    int r = n >> 6;
    float dxv = dirs[3*r + 0], dyv = dirs[3*r + 1], dzv = dirs[3*r + 2];
    float inv = rsqrtf(dxv*dxv + dyv*dyv + dzv*dzv);
    float X = dxv * inv, Y = dyv * inv, Z = dzv * inv;
    float xx = X * X, yy = Y * Y, zz = Z * Z;

    float ci[31];
    ci[0]  = 0.28209479177387814f;
    ci[1]  = -0.4886025119029199f * Y;
    ci[2]  = 0.4886025119029199f * Z;
    ci[3]  = -0.4886025119029199f * X;
    ci[4]  = 1.0925484305920792f * X * Y;
    ci[5]  = -1.0925484305920792f * Y * Z;
    ci[6]  = 0.31539156525252005f * (3.0f * zz - 1.0f);
    ci[7]  = -1.0925484305920792f * X * Z;
    ci[8]  = 0.5462742152960396f * (xx - yy);
    ci[9]  = -0.5900435899266435f * Y * (3.0f * xx - yy);
    ci[10] = 2.890611442640554f * X * Y * Z;
    ci[11] = -0.4570457994644658f * Y * (5.0f * zz - 1.0f);
    ci[12] = 0.3731763325901154f * Z * (5.0f * zz - 3.0f);
    ci[13] = -0.4570457994644658f * X * (5.0f * zz - 1.0f);
    ci[14] = 1.445305721320277f * Z * (xx - yy);
    ci[15] = -0.5900435899266435f * X * (xx - 3.0f * yy);
#pragma unroll
    for (int g = 0; g < 15; g++) ci[16 + g] = ov[g];

    // ---- h2 = relu(ci @ Wc1[31,64]) --- packed f32x2 ----
    float h2[64];
    {
        unsigned long long acc[32];
#pragma unroll
        for (int k = 0; k < 32; k++) acc[k] = 0ull;
#pragma unroll
        for (int i = 0; i < 31; i++) {
            unsigned long long fp = pack2(ci[i]);
            const ulonglong2* wrow = (const ulonglong2*)(sC1 + i * 64);
#pragma unroll
            for (int og = 0; og < 16; og++) {
                ulonglong2 w = wrow[og];
                ffma2(acc[2*og],     fp, w.x);
                ffma2(acc[2*og + 1], fp, w.y);
            }
        }
#pragma unroll
        for (int k = 0; k < 32; k++) {
            float lo, hi;
            unpack2(acc[k], lo, hi);
            h2[2*k]   = fmaxf(lo, 0.f);
            h2[2*k+1] = fmaxf(hi, 0.f);
        }
    }

    // ---- h3 = relu(h2 @ Wc2[64,64]) --- packed f32x2 ----
    float h3[64];
    {
        unsigned long long acc[32];
#pragma unroll
        for (int k = 0; k < 32; k++) acc[k] = 0ull;
#pragma unroll
        for (int i = 0; i < 64; i++) {
            unsigned long long fp = pack2(h2[i]);
            const ulonglong2* wrow = (const ulonglong2*)(sC2 + i * 64);
#pragma unroll
            for (int og = 0; og < 16; og++) {
                ulonglong2 w = wrow[og];
                ffma2(acc[2*og],     fp, w.x);
                ffma2(acc[2*og + 1], fp, w.y);
            }
        }
#pragma unroll
        for (int k = 0; k < 32; k++) {
            float lo, hi;
            unpack2(acc[k], lo, hi);
            h3[2*k]   = fmaxf(lo, 0.f);
            h3[2*k+1] = fmaxf(hi, 0.f);
        }
    }

    // ---- rgb = sigmoid(h3 @ Wc3[64,3]) ----
    float r0 = 0.f, r1 = 0.f, r2 = 0.f;
#pragma unroll
    for (int i = 0; i < 64; i++) {
        float f = h3[i];
        r0 += f * sC3[i * 3 + 0];
        r1 += f * sC3[i * 3 + 1];
        r2 += f * sC3[i * 3 + 2];
    }

    float4 res;
    res.x = 1.0f / (1.0f + expf(-r0));
    res.y = 1.0f / (1.0f + expf(-r1));
    res.z = 1.0f / (1.0f + expf(-r2));
    res.w = density;
    *(float4*)(outp + 4 * n) = res;
}

// ---------------------------------------------------------------------------
// Launch
// ---------------------------------------------------------------------------
extern "C" void kernel_launch(void* const* d_in, const int* in_sizes, int n_in,
                              void* d_out, int out_size) {
    const float* pts  = (const float*)d_in[0];
    const float* dirs = (const float*)d_in[1];
    const float* ts   = (const float*)d_in[2];
    const float* yl0 = (const float*)d_in[3];  const float* yh0 = (const float*)d_in[4];
    const float* yl1 = (const float*)d_in[5];  const float* yh1 = (const float*)d_in[6];
    const float* yl2 = (const float*)d_in[7];  const float* yh2 = (const float*)d_in[8];
    const float* yl3 = (const float*)d_in[9];  const float* yh3 = (const float*)d_in[10];
    const float* yl4 = (const float*)d_in[11]; const float* yh4 = (const float*)d_in[12];
    const float* yl5 = (const float*)d_in[13]; const float* yh5 = (const float*)d_in[14];
    const float* Wsig1 = (const float*)d_in[15];
    const float* Wsig2 = (const float*)d_in[16];
    const float* Wc1   = (const float*)d_in[17];
    const float* Wc2   = (const float*)d_in[18];
    const float* Wc3   = (const float*)d_in[19];

    idwt_all<<<2736, 256>>>(yl0, yh0, yl1, yh1, yl2, yh2,
                            yl3, yh3, yl4, yh4, yl5, yh5);

    size_t dyn = 128 * FSTRIDE * sizeof(float);   // 33.3 KB dynamic
    wf_gather<<<NSAMP / 128, 128, dyn>>>(pts, ts);

    wf_mlp<<<NSAMP / 128, 128>>>(dirs, Wsig1, Wsig2, Wc1, Wc2, Wc3,
                                 (float*)d_out);
}

// round 6
// speedup vs baseline: 2.1431x; 1.1645x over previous
#include <cuda_runtime.h>
#include <math.h>

// ---------------------------------------------------------------------------
// Problem constants
// ---------------------------------------------------------------------------
#define NSAMP    524288      // 8192 rays * 64 samples

// combos: (0,1) (0,2) (0,3) (1,2) (1,3) (2,3)
// widths: 64,64,50,64,50,50  ->  W2: 128,128,100,128,100,100
// Interleaved plane-pair layout per combo: [Y][X][C=32][2] = (hi, lo)
// Pair sizes (floats): 2*128*W2*32 -> offsets identical to previous layout.
#define TOTAL_PLANE_FLOATS 5603328   // 21.4 MB

__device__ float g_planes[TOTAL_PLANE_FLOATS];
__device__ float g_feats[64 * NSAMP];          // 134 MB, feature-major

typedef unsigned long long ull;

// ---------------------------------------------------------------------------
// Packed dual-fp32 helpers (sm_100 f32x2 pipe; IEEE-identical per half)
// ---------------------------------------------------------------------------
__device__ __forceinline__ ull pack2(float f) {
    ull r;
    asm("mov.b64 %0, {%1, %1};" : "=l"(r) : "f"(f));
    return r;
}
__device__ __forceinline__ void ffma2(ull& d, ull a, ull b) {
    asm("fma.rn.f32x2 %0, %1, %2, %0;" : "+l"(d) : "l"(a), "l"(b));
}
__device__ __forceinline__ void mul2(ull& d, ull a, ull b) {
    asm("mul.rn.f32x2 %0, %1, %2;" : "=l"(d) : "l"(a), "l"(b));
}
__device__ __forceinline__ void unpack2(ull v, float& lo, float& hi) {
    asm("mov.b64 {%0, %1}, %2;" : "=f"(lo), "=f"(hi) : "l"(v));
}

// ---------------------------------------------------------------------------
// IDWT precompute, all 6 combos in one kernel. One thread per
// (channel, coeff-pixel) -> writes 2x2 quad of (hi,lo) float2 pairs.
// ---------------------------------------------------------------------------
template <int W, int W2, int OFF>
__device__ __forceinline__ void idwt_body(const float* __restrict__ yl,
                                          const float* __restrict__ yh,
                                          int idx) {
    if (idx >= 32 * 64 * W) return;

    int j0   = idx % W;
    int rest = idx / W;
    int i0   = rest & 63;
    int c    = rest >> 6;

    float a  = yl[(c * 64 + i0) * W + j0];
    float lh = yh[((c * 3 + 0) * 64 + i0) * W + j0];
    float hl = yh[((c * 3 + 1) * 64 + i0) * W + j0];
    float hh = yh[((c * 3 + 2) * 64 + i0) * W + j0];

    float ee = 0.5f * (a + lh + hl + hh);
    float eo = 0.5f * (a + lh - hl - hh);
    float oe = 0.5f * (a - lh + hl - hh);
    float oo = 0.5f * (a - lh - hl + hh);
    float lo = 0.5f * a;

    int fi = OFF + ((2 * i0) * W2 + 2 * j0) * 64 + 2 * c;   // even float index
    *(float2*)(g_planes + fi)                = make_float2(ee, lo);
    *(float2*)(g_planes + fi + 64)           = make_float2(eo, lo);
    *(float2*)(g_planes + fi + W2 * 64)      = make_float2(oe, lo);
    *(float2*)(g_planes + fi + W2 * 64 + 64) = make_float2(oo, lo);
}

// block ranges (256 thr/blk): c0 [0,512) c1 [512,1024) c2 [1024,1424)
//                             c3 [1424,1936) c4 [1936,2336) c5 [2336,2736)
__global__ __launch_bounds__(256) void idwt_all(
    const float* __restrict__ yl0, const float* __restrict__ yh0,
    const float* __restrict__ yl1, const float* __restrict__ yh1,
    const float* __restrict__ yl2, const float* __restrict__ yh2,
    const float* __restrict__ yl3, const float* __restrict__ yh3,
    const float* __restrict__ yl4, const float* __restrict__ yh4,
    const float* __restrict__ yl5, const float* __restrict__ yh5) {
    int b = blockIdx.x;
    int t = threadIdx.x;
    if      (b <  512) idwt_body<64, 128,       0>(yl0, yh0, (b       ) * 256 + t);
    else if (b < 1024) idwt_body<64, 128, 1048576>(yl1, yh1, (b -  512) * 256 + t);
    else if (b < 1424) idwt_body<50, 100, 2097152>(yl2, yh2, (b - 1024) * 256 + t);
    else if (b < 1936) idwt_body<64, 128, 2916352>(yl3, yh3, (b - 1424) * 256 + t);
    else if (b < 2336) idwt_body<50, 100, 3964928>(yl4, yh4, (b - 1936) * 256 + t);
    else               idwt_body<50, 100, 4784128>(yl5, yh5, (b - 2336) * 256 + t);
}

// ---------------------------------------------------------------------------
// Gather: per-lane precompute of (encoded offset, wy, wx) per combo.
// Offset encoding: bits[0:24) = OFF + (y0*W2+x0)*64 (< 2^23),
//                  bit 24 = (x1>x0), bit 25 = (y1>y0).
// ---------------------------------------------------------------------------
template <int W2, int OFF, int J, int K>
__device__ __forceinline__ void prep(const float p4[4], int& oenc,
                                     float& wy, float& wx) {
    float y = (p4[J] + 1.0f) * 0.5f * 127.0f;
    float x = (p4[K] + 1.0f) * 0.5f * (float)(W2 - 1);

    float yf = fminf(fmaxf(floorf(y), 0.0f), 127.0f);
    float xf = fminf(fmaxf(floorf(x), 0.0f), (float)(W2 - 1));
    int y0 = (int)yf, x0 = (int)xf;
    int y1 = min(y0 + 1, 127);
    int x1 = min(x0 + 1, W2 - 1);
    wy = fminf(fmaxf(y - yf, 0.0f), 1.0f);
    wx = fminf(fmaxf(x - xf, 0.0f), 1.0f);

    oenc = (OFF + (y0 * W2 + x0) * 64)
         | ((x1 > x0) ? (1 << 24) : 0)
         | ((y1 > y0) ? (1 << 25) : 0);
}

// In-loop sampling: decode + 4x LDG.64 + packed bilerp, multiply into prod.
template <int DYC>   // DYC = W2*64
__device__ __forceinline__ void samp(int oenc, float wy, float wx,
                                     int lane2, ull& prod) {
    int base = (oenc & 0xFFFFFF) + lane2;
    int dx = ((oenc >> 24) & 1) << 6;            // 0 or 64
    int dy = (oenc & (1 << 25)) ? DYC : 0;

    float om_y = 1.0f - wy, om_x = 1.0f - wx;
    ull w00 = pack2(om_y * om_x);
    ull w01 = pack2(om_y * wx);
    ull w10 = pack2(wy * om_x);
    ull w11 = pack2(wy * wx);

    ull c00 = *(const ull*)(g_planes + base);
    ull c01 = *(const ull*)(g_planes + base + dx);
    ull c10 = *(const ull*)(g_planes + base + dy);
    ull c11 = *(const ull*)(g_planes + base + dy + dx);

    ull acc = 0ull;
    ffma2(acc, w00, c00);
    ffma2(acc, w01, c01);
    ffma2(acc, w10, c10);
    ffma2(acc, w11, c11);
    mul2(prod, prod, acc);
}

// ---------------------------------------------------------------------------
// Kernel A: gather -> feature-major scratch.
// Transpose buffer: per warp 32 samples * 69 floats (h at +lane, l at +34+lane).
// ---------------------------------------------------------------------------
#define TSTRIDE 69
#define WARPBUF (32 * TSTRIDE)   // 2208 floats per warp

__global__ __launch_bounds__(128) void wf_gather(
    const float* __restrict__ pts, const float* __restrict__ ts) {

    extern __shared__ float wfbuf[];   // 4 warps * WARPBUF floats = 34.5 KB

    int lane = threadIdx.x & 31;
    int warp = threadIdx.x >> 5;
    int lane2 = 2 * lane;
    int n = blockIdx.x * 128 + threadIdx.x;

    float p4[4];
    p4[0] = pts[3*n + 0];
    p4[1] = pts[3*n + 1];
    p4[2] = pts[3*n + 2];
    p4[3] = ts[n >> 6] * 2.0f - 1.0f;

    // Per-lane precompute for this lane's sample, all 6 combos.
    int   oe0, oe1, oe2, oe3, oe4, oe5;
    float wy0, wy1, wy2, wy3, wy4, wy5;
    float wx0, wx1, wx2, wx3, wx4, wx5;
    prep<128,       0, 0, 1>(p4, oe0, wy0, wx0);
    prep<128, 1048576, 0, 2>(p4, oe1, wy1, wx1);
    prep<100, 2097152, 0, 3>(p4, oe2, wy2, wx2);
    prep<128, 2916352, 1, 2>(p4, oe3, wy3, wx3);
    prep<100, 3964928, 1, 3>(p4, oe4, wy4, wx4);
    prep<100, 4784128, 2, 3>(p4, oe5, wy5, wx5);

    float* wf = wfbuf + warp * WARPBUF;

#pragma unroll 1
    for (int s = 0; s < 32; s++) {
        ull prod = pack2(1.0f);

#define DO_COMBO(OE, WY, WX, DYC)                                  \
        {                                                          \
            int   o  = __shfl_sync(0xffffffffu, OE, s);            \
            float a_ = __shfl_sync(0xffffffffu, WY, s);            \
            float b_ = __shfl_sync(0xffffffffu, WX, s);            \
            samp<DYC>(o, a_, b_, lane2, prod);                     \
        }
        DO_COMBO(oe0, wy0, wx0, 8192)
        DO_COMBO(oe1, wy1, wx1, 8192)
        DO_COMBO(oe2, wy2, wx2, 6400)
        DO_COMBO(oe3, wy3, wx3, 8192)
        DO_COMBO(oe4, wy4, wx4, 6400)
        DO_COMBO(oe5, wy5, wx5, 6400)
#undef DO_COMBO

        float fh, fl;
        unpack2(prod, fh, fl);
        wf[s * TSTRIDE + lane]      = fh;
        wf[s * TSTRIDE + 34 + lane] = fl;
    }
    __syncwarp();

    // Read back own sample (row = lane), write feature-major coalesced.
    const float* my = wf + lane * TSTRIDE;
#pragma unroll
    for (int j = 0; j < 32; j++)  g_feats[j * NSAMP + n] = my[j];
#pragma unroll
    for (int j = 32; j < 64; j++) g_feats[j * NSAMP + n] = my[j + 2];
}

// ---------------------------------------------------------------------------
// Kernel B: MLP chain with packed f32x2 FFMA. Static smem weights (44.5 KB).
// ---------------------------------------------------------------------------
__global__ __launch_bounds__(128) void wf_mlp(
    const float* __restrict__ dirs,
    const float* __restrict__ Wsig1, const float* __restrict__ Wsig2,
    const float* __restrict__ Wc1, const float* __restrict__ Wc2,
    const float* __restrict__ Wc3, float* __restrict__ outp) {

    __shared__ __align__(16) float sW1[64 * 64];
    __shared__ __align__(16) float sW2[64 * 16];
    __shared__ __align__(16) float sC1[32 * 64];
    __shared__ __align__(16) float sC2[64 * 64];
    __shared__ float sC3[64 * 3];

    for (int i = threadIdx.x; i < 64*64; i += 128) sW1[i] = Wsig1[i];
    for (int i = threadIdx.x; i < 64*16; i += 128) sW2[i] = Wsig2[i];
    for (int i = threadIdx.x; i < 31*64; i += 128) sC1[i] = Wc1[i];
    for (int i = threadIdx.x; i < 64*64; i += 128) sC2[i] = Wc2[i];
    for (int i = threadIdx.x; i < 64*3;  i += 128) sC3[i] = Wc3[i];
    __syncthreads();

    int n = blockIdx.x * 128 + threadIdx.x;

    float fv[64];
#pragma unroll
    for (int i = 0; i < 64; i++) fv[i] = g_feats[i * NSAMP + n];

    // ---- MLP1: h = relu(fv @ Wsig1[64,64]) ----
    float h[64];
    {
        ull acc[32];
#pragma unroll
        for (int k = 0; k < 32; k++) acc[k] = 0ull;
#pragma unroll
        for (int i = 0; i < 64; i++) {
            ull fp = pack2(fv[i]);
            const ulonglong2* wrow = (const ulonglong2*)(sW1 + i * 64);
#pragma unroll
            for (int og = 0; og < 16; og++) {
                ulonglong2 w = wrow[og];
                ffma2(acc[2*og],     fp, w.x);
                ffma2(acc[2*og + 1], fp, w.y);
            }
        }
#pragma unroll
        for (int k = 0; k < 32; k++) {
            float lo, hi;
            unpack2(acc[k], lo, hi);
            h[2*k]   = fmaxf(lo, 0.f);
            h[2*k+1] = fmaxf(hi, 0.f);
        }
    }

    // ---- out = h @ Wsig2[64,16] ----
    float ov[16];
    {
        ull acc[8];
#pragma unroll
        for (int k = 0; k < 8; k++) acc[k] = 0ull;
#pragma unroll
        for (int i = 0; i < 64; i++) {
            ull fp = pack2(h[i]);
            const ulonglong2* wrow = (const ulonglong2*)(sW2 + i * 16);
#pragma unroll
            for (int og = 0; og < 4; og++) {
                ulonglong2 w = wrow[og];
                ffma2(acc[2*og],     fp, w.x);
                ffma2(acc[2*og + 1], fp, w.y);
            }
        }
#pragma unroll
        for (int k = 0; k < 8; k++) unpack2(acc[k], ov[2*k], ov[2*k+1]);
    }
    float density = expf(fminf(fmaxf(ov[15], -15.0f), 15.0f));

    // ---- SH degree-4 encoding ----
    int r = n >> 6;
    float dxv = dirs[3*r + 0], dyv = dirs[3*r + 1], dzv = dirs[3*r + 2];
    float inv = rsqrtf(dxv*dxv + dyv*dyv + dzv*dzv);
    float X = dxv * inv, Y = dyv * inv, Z = dzv * inv;
    float xx = X * X, yy = Y * Y, zz = Z * Z;

    float ci[31];
    ci[0]  = 0.28209479177387814f;
    ci[1]  = -0.4886025119029199f * Y;
    ci[2]  = 0.4886025119029199f * Z;
    ci[3]  = -0.4886025119029199f * X;
    ci[4]  = 1.0925484305920792f * X * Y;
    ci[5]  = -1.0925484305920792f * Y * Z;
    ci[6]  = 0.31539156525252005f * (3.0f * zz - 1.0f);
    ci[7]  = -1.0925484305920792f * X * Z;
    ci[8]  = 0.5462742152960396f * (xx - yy);
    ci[9]  = -0.5900435899266435f * Y * (3.0f * xx - yy);
    ci[10] = 2.890611442640554f * X * Y * Z;
    ci[11] = -0.4570457994644658f * Y * (5.0f * zz - 1.0f);
    ci[12] = 0.3731763325901154f * Z * (5.0f * zz - 3.0f);
    ci[13] = -0.4570457994644658f * X * (5.0f * zz - 1.0f);
    ci[14] = 1.445305721320277f * Z * (xx - yy);
    ci[15] = -0.5900435899266435f * X * (xx - 3.0f * yy);
#pragma unroll
    for (int g = 0; g < 15; g++) ci[16 + g] = ov[g];

    // ---- h2 = relu(ci @ Wc1[31,64]) ----
    float h2[64];
    {
        ull acc[32];
#pragma unroll
        for (int k = 0; k < 32; k++) acc[k] = 0ull;
#pragma unroll
        for (int i = 0; i < 31; i++) {
            ull fp = pack2(ci[i]);
            const ulonglong2* wrow = (const ulonglong2*)(sC1 + i * 64);
#pragma unroll
            for (int og = 0; og < 16; og++) {
                ulonglong2 w = wrow[og];
                ffma2(acc[2*og],     fp, w.x);
                ffma2(acc[2*og + 1], fp, w.y);
            }
        }
#pragma unroll
        for (int k = 0; k < 32; k++) {
            float lo, hi;
            unpack2(acc[k], lo, hi);
            h2[2*k]   = fmaxf(lo, 0.f);
            h2[2*k+1] = fmaxf(hi, 0.f);
        }
    }

    // ---- h3 = relu(h2 @ Wc2[64,64]) ----
    float h3[64];
    {
        ull acc[32];
#pragma unroll
        for (int k = 0; k < 32; k++) acc[k] = 0ull;
#pragma unroll
        for (int i = 0; i < 64; i++) {
            ull fp = pack2(h2[i]);
            const ulonglong2* wrow = (const ulonglong2*)(sC2 + i * 64);
#pragma unroll
            for (int og = 0; og < 16; og++) {
                ulonglong2 w = wrow[og];
                ffma2(acc[2*og],     fp, w.x);
                ffma2(acc[2*og + 1], fp, w.y);
            }
        }
#pragma unroll
        for (int k = 0; k < 32; k++) {
            float lo, hi;
            unpack2(acc[k], lo, hi);
            h3[2*k]   = fmaxf(lo, 0.f);
            h3[2*k+1] = fmaxf(hi, 0.f);
        }
    }

    // ---- rgb = sigmoid(h3 @ Wc3[64,3]) ----
    float r0 = 0.f, r1 = 0.f, r2 = 0.f;
#pragma unroll
    for (int i = 0; i < 64; i++) {
        float f = h3[i];
        r0 += f * sC3[i * 3 + 0];
        r1 += f * sC3[i * 3 + 1];
        r2 += f * sC3[i * 3 + 2];
    }

    float4 res;
    res.x = 1.0f / (1.0f + expf(-r0));
    res.y = 1.0f / (1.0f + expf(-r1));
    res.z = 1.0f / (1.0f + expf(-r2));
    res.w = density;
    *(float4*)(outp + 4 * n) = res;
}

// ---------------------------------------------------------------------------
// Launch
// ---------------------------------------------------------------------------
extern "C" void kernel_launch(void* const* d_in, const int* in_sizes, int n_in,
                              void* d_out, int out_size) {
    const float* pts  = (const float*)d_in[0];
    const float* dirs = (const float*)d_in[1];
    const float* ts   = (const float*)d_in[2];
    const float* yl0 = (const float*)d_in[3];  const float* yh0 = (const float*)d_in[4];
    const float* yl1 = (const float*)d_in[5];  const float* yh1 = (const float*)d_in[6];
    const float* yl2 = (const float*)d_in[7];  const float* yh2 = (const float*)d_in[8];
    const float* yl3 = (const float*)d_in[9];  const float* yh3 = (const float*)d_in[10];
    const float* yl4 = (const float*)d_in[11]; const float* yh4 = (const float*)d_in[12];
    const float* yl5 = (const float*)d_in[13]; const float* yh5 = (const float*)d_in[14];
    const float* Wsig1 = (const float*)d_in[15];
    const float* Wsig2 = (const float*)d_in[16];
    const float* Wc1   = (const float*)d_in[17];
    const float* Wc2   = (const float*)d_in[18];
    const float* Wc3   = (const float*)d_in[19];

    idwt_all<<<2736, 256>>>(yl0, yh0, yl1, yh1, yl2, yh2,
                            yl3, yh3, yl4, yh4, yl5, yh5);

    size_t dyn = 4 * WARPBUF * sizeof(float);   // 34.5 KB dynamic
    wf_gather<<<NSAMP / 128, 128, dyn>>>(pts, ts);

    wf_mlp<<<NSAMP / 128, 128>>>(dirs, Wsig1, Wsig2, Wc1, Wc2, Wc3,
                                 (float*)d_out);
}